// round 5
// baseline (speedup 1.0000x reference)
#include <cuda_runtime.h>
#include <cuda_fp16.h>

#define BATCH 8
#define NPX   (512*512)          // 262144 pixels per sample
#define BPS   64                 // K1 blocks per sample -> 512 blocks
#define NBIN1 2048               // top-12-bit half histogram
#define CH3   64                 // K2 chunks per (arr,sample) -> 1024 blocks
#define EPS   1e-6f
#define SCALE_D 1099511627776.0  // 2^40 fixed-point scale

// ---------------- device scratch (static; zero-init at load; epoch-managed) ----
__device__ __half    g_valA[BATCH*NPX];             // alpha-diff values (fp16)
__device__ __half    g_valC[BATCH*NPX];             // comp-diff values (fp16)
__device__ unsigned  g_count[2][BATCH];             // per-epoch unknown counts
__device__ unsigned  g_hist1[2][2][BATCH][NBIN1];   // per-epoch 12-bit histograms
__device__ unsigned  g_hist16[2][BATCH][16];        // low-4-bit sub-hist of cut bin
__device__ unsigned  g_pfx[2][BATCH];               // selected 12-bit prefix
__device__ unsigned  g_krem[2][BATCH];              // elements needed from cut bin
__device__ unsigned long long g_sum[2][BATCH];      // fixed-point sum above cut bin
__device__ int       g_epoch;                       // toggled by last k_sumpass block
__device__ unsigned  g_done;                        // k_sumpass completion counter

// ---------------- K1: fused compute + count + warp-aggregated 12-bit hist ----
__global__ __launch_bounds__(256, 5) void k_compute(
    const float* __restrict__ image, const float* __restrict__ alpha,
    const float* __restrict__ pred,  const int*   __restrict__ trimap,
    const float* __restrict__ fg,    const float* __restrict__ bg)
{
    __shared__ unsigned shA[NBIN1];
    __shared__ unsigned shC[NBIN1];
    __shared__ unsigned shCnt;
    #pragma unroll
    for (int i = threadIdx.x; i < NBIN1; i += 256) { shA[i] = 0u; shC[i] = 0u; }
    if (threadIdx.x == 0) shCnt = 0u;

    const int e = g_epoch;
    // zero the OTHER epoch's accumulators (fully consumed by the previous run)
    if (threadIdx.x < 64)
        ((unsigned*)g_hist1[1 - e])[blockIdx.x * 64u + threadIdx.x] = 0u;
    if (blockIdx.x == 0 && threadIdx.x < BATCH) g_count[1 - e][threadIdx.x] = 0u;
    __syncthreads();

    const int b     = blockIdx.x >> 6;              // / BPS
    const int chunk = blockIdx.x & (BPS - 1);
    const int base  = chunk * (NPX / BPS);          // 4096-pixel chunk
    const int CH4   = NPX / 4;                      // channel stride in float4
    const int lane  = threadIdx.x & 31;

    const float4* al4 = (const float4*)(alpha  + (size_t)b * NPX + base);
    const float4* pr4 = (const float4*)(pred   + (size_t)b * NPX + base);
    const int4*   tm4 = (const int4*)  (trimap + (size_t)b * NPX + base);
    const float4* im4 = (const float4*)(image  + (size_t)b * 3 * NPX + base);
    const float4* fg4 = (const float4*)(fg     + (size_t)b * 3 * NPX + base);
    const float4* bg4 = (const float4*)(bg     + (size_t)b * 3 * NPX + base);
    uint2* oA = (uint2*)(g_valA + (size_t)b * NPX + base);
    uint2* oC = (uint2*)(g_valC + (size_t)b * NPX + base);

    const unsigned short HEPS  = __half_as_ushort(__float2half_rn(EPS));
    const unsigned short HEPS3 = __half_as_ushort(__float2half_rn(3.0f * EPS));

    unsigned cnt = 0;
    for (int it = 0; it < (NPX / BPS) / 4 / 256; it++) {   // 4 iterations
        const int i = it * 256 + threadIdx.x;
        const int4   t = __ldcs(tm4 + i);
        const float4 a = __ldcs(al4 + i);
        const float4 p = __ldcs(pr4 + i);

        float da[4], dc[4];
        #pragma unroll
        for (int j = 0; j < 4; j++) {
            da[j] = fmaxf(fabsf(fmaf(((const float*)&a)[j], 1.0f/255.0f,
                                     -((const float*)&p)[j])), EPS);
            dc[j] = 0.0f;
        }
        #pragma unroll
        for (int ch = 0; ch < 3; ch++) {            // channel-incremental
            const float4 im = __ldcs(im4 + i + ch * CH4);
            const float4 ff = __ldcs(fg4 + i + ch * CH4);
            const float4 gg = __ldcs(bg4 + i + ch * CH4);
            #pragma unroll
            for (int j = 0; j < 4; j++) {
                float pj = ((const float*)&p)[j];
                float tt = fmaf(((const float*)&ff)[j] - ((const float*)&gg)[j], pj,
                                ((const float*)&gg)[j]);
                dc[j] += fmaxf(fabsf(((const float*)&im)[j] - tt), EPS);
            }
        }
        unsigned short ha[4], hc[4];
        #pragma unroll
        for (int j = 0; j < 4; j++) {
            const bool u = (((const int*)&t)[j] == 128);
            unsigned short hda = __half_as_ushort(__float2half_rn(da[j]));
            unsigned short hdc = __half_as_ushort(__float2half_rn(dc[j]));
            ha[j] = u ? hda : HEPS;
            hc[j] = u ? hdc : HEPS3;
            cnt += u;
            // warp-aggregated histogram updates (degree-1 atomics)
            unsigned binA = u ? (unsigned)(hda >> 4) : 0xFFFFu;
            unsigned mA = __match_any_sync(0xFFFFFFFFu, binA);
            if (binA != 0xFFFFu && (unsigned)(__ffs(mA) - 1) == (unsigned)lane)
                atomicAdd(&shA[binA], (unsigned)__popc(mA));
            unsigned binC = u ? (unsigned)(hdc >> 4) : 0xFFFFu;
            unsigned mC = __match_any_sync(0xFFFFFFFFu, binC);
            if (binC != 0xFFFFu && (unsigned)(__ffs(mC) - 1) == (unsigned)lane)
                atomicAdd(&shC[binC], (unsigned)__popc(mC));
        }
        uint2 va, vc;
        va.x = (unsigned)ha[0] | ((unsigned)ha[1] << 16);
        va.y = (unsigned)ha[2] | ((unsigned)ha[3] << 16);
        vc.x = (unsigned)hc[0] | ((unsigned)hc[1] << 16);
        vc.y = (unsigned)hc[2] | ((unsigned)hc[3] << 16);
        oA[i] = va;
        oC[i] = vc;
    }
    cnt = __reduce_add_sync(0xFFFFFFFFu, cnt);
    if ((threadIdx.x & 31) == 0 && cnt) atomicAdd(&shCnt, cnt);
    __syncthreads();
    if (threadIdx.x == 0 && shCnt) atomicAdd(&g_count[e][b], shCnt);
    #pragma unroll
    for (int i = threadIdx.x; i < NBIN1; i += 256) {
        unsigned v = shA[i]; if (v) atomicAdd(&g_hist1[e][0][b][i], v);
        v = shC[i];          if (v) atomicAdd(&g_hist1[e][1][b][i], v);
    }
}

// ---------------- K2: inline cut-scan + sum pass + fused finish (last block) ----
__global__ __launch_bounds__(256) void k_sumpass(float* __restrict__ out) {
    __shared__ unsigned s_seg[256];
    __shared__ unsigned s_pfx, s_krem;
    __shared__ unsigned sh16[16];
    __shared__ unsigned long long shs;
    __shared__ bool s_last;

    const int blk = blockIdx.x;                      // 2*BATCH*CH3 blocks
    const int arr = blk / (BATCH * CH3);
    const int b   = (blk / CH3) % BATCH;
    const int c   = blk % CH3;
    const int t   = threadIdx.x;
    const int e   = g_epoch;

    if (t < 16) sh16[t] = 0u;
    if (t == 0) { shs = 0ull; s_pfx = 0xFFFFFFFFu; s_krem = 0u; }

    // ---- inline descending scan of g_hist1[e][arr][b] to find cut bin ----
    const unsigned* hist = g_hist1[e][arr][b];
    uint4 h0 = *(const uint4*)&hist[2040 - 8 * t];   // t ascending = value descending
    uint4 h1 = *(const uint4*)&hist[2044 - 8 * t];
    unsigned seg = h0.x + h0.y + h0.z + h0.w + h1.x + h1.y + h1.z + h1.w;
    s_seg[t] = seg;
    __syncthreads();
    #pragma unroll
    for (int d = 1; d < 256; d <<= 1) {               // Hillis-Steele inclusive scan
        unsigned v = (t >= d) ? s_seg[t - d] : 0u;
        __syncthreads();
        s_seg[t] += v;
        __syncthreads();
    }
    const unsigned k = (unsigned)(int)floorf((float)g_count[e][b] * 0.7f);
    {
        unsigned incl = s_seg[t];
        unsigned excl = incl - seg;
        if (k > 0u && excl < k && incl >= k) {        // exactly one owner thread
            unsigned bins[8] = {h1.w, h1.z, h1.y, h1.x, h0.w, h0.z, h0.y, h0.x};
            unsigned cum = excl;
            #pragma unroll
            for (int j = 0; j < 8; j++) {
                cum += bins[j];
                if (cum >= k) {
                    s_pfx  = (unsigned)(2047 - 8 * t - j);
                    s_krem = k - (cum - bins[j]);     // >= 1
                    break;
                }
            }
        }
    }
    __syncthreads();
    const unsigned pfx = s_pfx;
    if (c == 0 && t == 0) { g_pfx[arr][b] = pfx; g_krem[arr][b] = s_krem; }

    // ---- main sum pass over this block's scratch chunk ----
    const __half* srcp = (arr ? g_valC : g_valA) + (size_t)b * NPX + c * (NPX / CH3);
    const uint4*  src  = (const uint4*)srcp;         // 8 halves per load

    float fsum = 0.0f;
    #pragma unroll
    for (int it = 0; it < (NPX / CH3) / 8 / 256; it++) {   // 2 iterations
        uint4 v = src[it * 256 + t];
        const unsigned wv[4] = {v.x, v.y, v.z, v.w};
        #pragma unroll
        for (int q = 0; q < 4; q++) {
            #pragma unroll
            for (int h = 0; h < 2; h++) {
                unsigned hb  = (wv[q] >> (16 * h)) & 0xFFFFu;
                unsigned bin = hb >> 4;
                if (bin > pfx) {
                    fsum += __half2float(__ushort_as_half((unsigned short)hb));
                } else if (bin == pfx) {
                    atomicAdd(&sh16[hb & 15u], 1u);
                }
            }
        }
    }
    #pragma unroll
    for (int o = 16; o; o >>= 1) fsum += __shfl_xor_sync(0xFFFFFFFFu, fsum, o);
    if ((t & 31) == 0 && fsum != 0.0f)
        atomicAdd(&shs, (unsigned long long)((double)fsum * SCALE_D));
    __syncthreads();
    if (t == 0 && shs) atomicAdd(&g_sum[arr][b], shs);
    if (t < 16) {
        unsigned v = sh16[t];
        if (v) atomicAdd(&g_hist16[arr][b][t], v);
    }

    // ---- last-block detection + fused finish ----
    __threadfence();
    __syncthreads();
    if (t == 0) s_last = (atomicAdd(&g_done, 1u) == (unsigned)(gridDim.x - 1));
    __syncthreads();
    if (!s_last) return;
    __threadfence();

    __shared__ double losses[2 * BATCH];
    if (t < 2 * BATCH) {
        const int a2 = t / BATCH, b2 = t % BATCH;
        const int kk = (int)floorf((float)g_count[e][b2] * 0.7f);
        double loss = 0.0;
        if (kk > 0) {
            double total = (double)g_sum[a2][b2] / SCALE_D;
            unsigned rem = g_krem[a2][b2];
            const unsigned p2 = g_pfx[a2][b2];
            for (int sub = 15; sub >= 0 && rem > 0u; sub--) {
                unsigned cc = g_hist16[a2][b2][sub];
                if (!cc) continue;
                unsigned take = cc < rem ? cc : rem;
                float v = __half2float(__ushort_as_half((unsigned short)((p2 << 4) | (unsigned)sub)));
                total += (double)take * (double)v;
                rem -= take;
            }
            loss = total / ((double)kk + 1e-6);
        }
        losses[t] = loss;
    }
    __syncthreads();
    if (t == 0) {
        double sA = 0.0, sC = 0.0;
        for (int i = 0; i < BATCH; i++) { sA += losses[i]; sC += losses[BATCH + i]; }
        out[0] = 0.5f * (float)(sA / (double)BATCH) + 0.5f * (float)(sC / (double)BATCH);
    }
    // re-zero small accumulators + advance epoch for next graph replay
    ((unsigned*)g_hist16)[t] = 0u;                    // 256 words
    if (t < 2 * BATCH) ((unsigned long long*)g_sum)[t] = 0ull;
    if (t == 0) { g_done = 0u; g_epoch = 1 - e; }
}

// ---------------- launch ----------------
extern "C" void kernel_launch(void* const* d_in, const int* in_sizes, int n_in,
                              void* d_out, int out_size)
{
    const float* image  = (const float*)d_in[0];
    const float* alpha  = (const float*)d_in[1];
    const float* pred   = (const float*)d_in[2];
    const int*   trimap = (const int*)  d_in[3];
    const float* fg     = (const float*)d_in[4];
    const float* bg     = (const float*)d_in[5];

    k_compute<<<BATCH * BPS, 256>>>(image, alpha, pred, trimap, fg, bg);
    k_sumpass<<<2 * BATCH * CH3, 256>>>((float*)d_out);
}

// round 6
// speedup vs baseline: 1.3949x; 1.3949x over previous
#include <cuda_runtime.h>
#include <cuda_fp16.h>

#define BATCH 8
#define NPX   (512*512)          // 262144 pixels per sample
#define BPS   64                 // K1 blocks per sample -> 512 blocks (1 wave @6/SM)
#define NBIN1 2048               // top-12-bit half histogram
#define CH3   64                 // K2 chunks per (arr,sample) -> 1024 blocks
#define EPS   1e-6f
#define SCALE_D 1099511627776.0  // 2^40 fixed-point scale

// ---------------- device scratch (static; zero-init at load, re-zeroed by k_final) ----
__device__ __half    g_valA[BATCH*NPX];          // alpha-diff values (fp16)
__device__ __half    g_valC[BATCH*NPX];          // comp-diff values (fp16)
__device__ unsigned  g_count[BATCH];             // # unknown pixels
__device__ unsigned  g_hist1[2][BATCH][NBIN1];   // top-12-bit histograms
__device__ unsigned  g_hist16[2][BATCH][16];     // low-4-bit sub-histogram of cut bin
__device__ unsigned  g_pfx[2][BATCH];            // selected 12-bit prefix (for k_final)
__device__ unsigned  g_krem[2][BATCH];           // elements still needed from cut bin
__device__ unsigned long long g_sum[2][BATCH];   // fixed-point sum of values above cut bin

// ---------------- K1: fused value compute + count + 12-bit hist ----
__global__ __launch_bounds__(256, 6) void k_compute(
    const float* __restrict__ image, const float* __restrict__ alpha,
    const float* __restrict__ pred,  const int*   __restrict__ trimap,
    const float* __restrict__ fg,    const float* __restrict__ bg)
{
    __shared__ unsigned shA[NBIN1];
    __shared__ unsigned shC[NBIN1];
    __shared__ unsigned shCnt;
    #pragma unroll
    for (int i = threadIdx.x; i < NBIN1; i += 256) { shA[i] = 0u; shC[i] = 0u; }
    if (threadIdx.x == 0) shCnt = 0u;
    __syncthreads();

    const int b     = blockIdx.x >> 6;              // / BPS
    const int chunk = blockIdx.x & (BPS - 1);
    const int base  = chunk * (NPX / BPS);          // 4096-pixel chunk
    const int CH4   = NPX / 4;                      // channel stride in float4

    const float4* al4 = (const float4*)(alpha  + (size_t)b * NPX + base);
    const float4* pr4 = (const float4*)(pred   + (size_t)b * NPX + base);
    const int4*   tm4 = (const int4*)  (trimap + (size_t)b * NPX + base);
    const float4* im4 = (const float4*)(image  + (size_t)b * 3 * NPX + base);
    const float4* fg4 = (const float4*)(fg     + (size_t)b * 3 * NPX + base);
    const float4* bg4 = (const float4*)(bg     + (size_t)b * 3 * NPX + base);
    uint2* oA = (uint2*)(g_valA + (size_t)b * NPX + base);
    uint2* oC = (uint2*)(g_valC + (size_t)b * NPX + base);

    const unsigned short HEPS  = __half_as_ushort(__float2half_rn(EPS));
    const unsigned short HEPS3 = __half_as_ushort(__float2half_rn(3.0f * EPS));

    unsigned cnt = 0;
    for (int it = 0; it < (NPX / BPS) / 4 / 256; it++) {   // 4 iterations
        const int i = it * 256 + threadIdx.x;
        const int4   t = __ldcs(tm4 + i);
        const float4 a = __ldcs(al4 + i);
        const float4 p = __ldcs(pr4 + i);

        float da[4], dc[4];
        #pragma unroll
        for (int j = 0; j < 4; j++) {
            da[j] = fmaxf(fabsf(fmaf(((const float*)&a)[j], 1.0f/255.0f,
                                     -((const float*)&p)[j])), EPS);
            dc[j] = 0.0f;
        }
        #pragma unroll
        for (int ch = 0; ch < 3; ch++) {            // channel-incremental: low live-reg count
            const float4 im = __ldcs(im4 + i + ch * CH4);
            const float4 ff = __ldcs(fg4 + i + ch * CH4);
            const float4 gg = __ldcs(bg4 + i + ch * CH4);
            #pragma unroll
            for (int j = 0; j < 4; j++) {
                float pj = ((const float*)&p)[j];
                float tt = fmaf(((const float*)&ff)[j] - ((const float*)&gg)[j], pj,
                                ((const float*)&gg)[j]);
                dc[j] += fmaxf(fabsf(((const float*)&im)[j] - tt), EPS);
            }
        }
        unsigned short ha[4], hc[4];
        #pragma unroll
        for (int j = 0; j < 4; j++) {
            const bool u = (((const int*)&t)[j] == 128);
            unsigned short hda = __half_as_ushort(__float2half_rn(da[j]));
            unsigned short hdc = __half_as_ushort(__float2half_rn(dc[j]));
            ha[j] = u ? hda : HEPS;
            hc[j] = u ? hdc : HEPS3;
            if (u) {
                atomicAdd(&shA[hda >> 4], 1u);
                atomicAdd(&shC[hdc >> 4], 1u);
                cnt++;
            }
        }
        uint2 va, vc;
        va.x = (unsigned)ha[0] | ((unsigned)ha[1] << 16);
        va.y = (unsigned)ha[2] | ((unsigned)ha[3] << 16);
        vc.x = (unsigned)hc[0] | ((unsigned)hc[1] << 16);
        vc.y = (unsigned)hc[2] | ((unsigned)hc[3] << 16);
        oA[i] = va;
        oC[i] = vc;
    }
    cnt = __reduce_add_sync(0xFFFFFFFFu, cnt);
    if ((threadIdx.x & 31) == 0 && cnt) atomicAdd(&shCnt, cnt);
    __syncthreads();
    if (threadIdx.x == 0 && shCnt) atomicAdd(&g_count[b], shCnt);
    #pragma unroll
    for (int i = threadIdx.x; i < NBIN1; i += 256) {
        unsigned v = shA[i]; if (v) atomicAdd(&g_hist1[0][b][i], v);
        v = shC[i];          if (v) atomicAdd(&g_hist1[1][b][i], v);
    }
}

// ---------------- K2: inline cut-scan (warp-level) + sum above cut + sub-hist ----
__global__ __launch_bounds__(256) void k_sumpass() {
    __shared__ unsigned s_wsum[8];
    __shared__ unsigned s_pfx, s_krem;
    __shared__ unsigned sh16[16];
    __shared__ unsigned long long shs;

    const int blk = blockIdx.x;                      // 2*BATCH*CH3 blocks
    const int arr = blk / (BATCH * CH3);
    const int b   = (blk / CH3) % BATCH;
    const int c   = blk % CH3;
    const int t   = threadIdx.x;
    const int lane = t & 31, w = t >> 5;

    if (t < 16) sh16[t] = 0u;
    if (t == 0) { shs = 0ull; s_pfx = 0xFFFFFFFFu; s_krem = 0u; }

    // ---- descending scan of g_hist1[arr][b]: thread t owns bins 2047-8t..2040-8t ----
    const unsigned* hist = g_hist1[arr][b];
    uint4 h0 = *(const uint4*)&hist[2040 - 8 * t];
    uint4 h1 = *(const uint4*)&hist[2044 - 8 * t];
    unsigned seg = h0.x + h0.y + h0.z + h0.w + h1.x + h1.y + h1.z + h1.w;

    // warp-level inclusive scan of seg (t ascending = value descending)
    unsigned incl = seg;
    #pragma unroll
    for (int d = 1; d < 32; d <<= 1) {
        unsigned v = __shfl_up_sync(0xFFFFFFFFu, incl, d);
        if (lane >= d) incl += v;
    }
    if (lane == 31) s_wsum[w] = incl;
    __syncthreads();
    if (t == 0) {                                    // serial scan of 8 warp totals
        unsigned run = 0;
        #pragma unroll
        for (int i = 0; i < 8; i++) { unsigned v = s_wsum[i]; s_wsum[i] = run; run += v; }
    }
    __syncthreads();
    incl += s_wsum[w];

    const unsigned k = (unsigned)(int)floorf((float)g_count[b] * 0.7f);
    {
        unsigned excl = incl - seg;
        if (k > 0u && excl < k && incl >= k) {        // exactly one owner thread
            unsigned bins[8] = {h1.w, h1.z, h1.y, h1.x, h0.w, h0.z, h0.y, h0.x};
            unsigned cum = excl;
            #pragma unroll
            for (int j = 0; j < 8; j++) {
                cum += bins[j];
                if (cum >= k) {
                    s_pfx  = (unsigned)(2047 - 8 * t - j);
                    s_krem = k - (cum - bins[j]);     // >= 1
                    break;
                }
            }
        }
    }
    __syncthreads();
    const unsigned pfx = s_pfx;
    if (c == 0 && t == 0) { g_pfx[arr][b] = pfx; g_krem[arr][b] = s_krem; }

    // ---- main sum pass over this block's scratch chunk ----
    const __half* srcp = (arr ? g_valC : g_valA) + (size_t)b * NPX + c * (NPX / CH3);
    const uint4*  src  = (const uint4*)srcp;         // 8 halves per load

    float fsum = 0.0f;
    #pragma unroll
    for (int it = 0; it < (NPX / CH3) / 8 / 256; it++) {   // 2 iterations
        uint4 v = src[it * 256 + t];
        const unsigned wv[4] = {v.x, v.y, v.z, v.w};
        #pragma unroll
        for (int q = 0; q < 4; q++) {
            #pragma unroll
            for (int h = 0; h < 2; h++) {
                unsigned hb  = (wv[q] >> (16 * h)) & 0xFFFFu;
                unsigned bin = hb >> 4;
                if (bin > pfx) {
                    fsum += __half2float(__ushort_as_half((unsigned short)hb));
                } else if (bin == pfx) {
                    atomicAdd(&sh16[hb & 15u], 1u);
                }
            }
        }
    }
    #pragma unroll
    for (int o = 16; o; o >>= 1) fsum += __shfl_xor_sync(0xFFFFFFFFu, fsum, o);
    if (lane == 0 && fsum != 0.0f)
        atomicAdd(&shs, (unsigned long long)((double)fsum * SCALE_D));
    __syncthreads();
    if (t == 0 && shs) atomicAdd(&g_sum[arr][b], shs);
    if (t < 16) {
        unsigned v = sh16[t];
        if (v) atomicAdd(&g_hist16[arr][b][t], v);
    }
}

// ---------------- K3: finish (block 0) + re-zero accumulators (all blocks) ----
__global__ __launch_bounds__(256) void k_final(float* __restrict__ out) {
    const int t = threadIdx.x;
    if (blockIdx.x != 0) {
        // zero g_hist1: 32768 words over 64 blocks, 2 words per thread
        unsigned base = (blockIdx.x - 1) * 512u + (unsigned)t;
        ((unsigned*)g_hist1)[base]        = 0u;
        ((unsigned*)g_hist1)[base + 256u] = 0u;
        return;
    }
    __shared__ double losses[2 * BATCH];
    if (t < 2 * BATCH) {
        const int arr = t / BATCH, b = t % BATCH;
        const int k = (int)floorf((float)g_count[b] * 0.7f);
        double loss = 0.0;
        if (k > 0) {
            double total = (double)g_sum[arr][b] / SCALE_D;
            unsigned rem = g_krem[arr][b];
            const unsigned pfx = g_pfx[arr][b];
            for (int sub = 15; sub >= 0 && rem > 0u; sub--) {
                unsigned cc = g_hist16[arr][b][sub];
                if (!cc) continue;
                unsigned take = cc < rem ? cc : rem;
                float v = __half2float(__ushort_as_half((unsigned short)((pfx << 4) | (unsigned)sub)));
                total += (double)take * (double)v;
                rem -= take;
            }
            loss = total / ((double)k + 1e-6);
        }
        losses[t] = loss;
    }
    __syncthreads();                                  // all reads of accumulators done
    if (t == 0) {
        double sA = 0.0, sC = 0.0;
        for (int b = 0; b < BATCH; b++) { sA += losses[b]; sC += losses[BATCH + b]; }
        out[0] = 0.5f * (float)(sA / (double)BATCH) + 0.5f * (float)(sC / (double)BATCH);
    }
    // re-zero small accumulators for the next graph replay
    ((unsigned*)g_hist16)[t] = 0u;                    // 256 words
    if (t < 2 * BATCH) ((unsigned long long*)g_sum)[t] = 0ull;
    if (t < BATCH)     g_count[t] = 0u;
}

// ---------------- launch ----------------
extern "C" void kernel_launch(void* const* d_in, const int* in_sizes, int n_in,
                              void* d_out, int out_size)
{
    const float* image  = (const float*)d_in[0];
    const float* alpha  = (const float*)d_in[1];
    const float* pred   = (const float*)d_in[2];
    const int*   trimap = (const int*)  d_in[3];
    const float* fg     = (const float*)d_in[4];
    const float* bg     = (const float*)d_in[5];

    k_compute<<<BATCH * BPS, 256>>>(image, alpha, pred, trimap, fg, bg);
    k_sumpass<<<2 * BATCH * CH3, 256>>>();
    k_final<<<65, 256>>>((float*)d_out);
}